// round 3
// baseline (speedup 1.0000x reference)
#include <cuda_runtime.h>

#define NN 50000
#define NE 800000
#define NG 256
#define IND 128
#define HID 64
#define EMB 128

// ---------------- scratch (device globals; no allocation) ----------------
__device__ int g_src[NE];
__device__ int g_dst[NE];
__device__ int g_batch[NN];
__device__ int g_is64_edge;
__device__ int g_is64_batch;

__device__ float g_deg[NN];
__device__ float g_dis[NN];
__device__ alignas(16) float g_h1[(size_t)NN * HID];   // x @ W1
__device__ alignas(16) float g_a1[(size_t)NN * HID];   // aggregated layer 1 (pre-bias)
__device__ alignas(16) float g_h2[(size_t)NN * EMB];   // relu(a1+b1) @ W2
__device__ alignas(16) float g_a2[(size_t)NN * EMB];   // aggregated layer 2 (pre-bias)
__device__ alignas(16) float g_pool[NG * EMB];
__device__ float g_cnt[NG];

// vector f32 reduction (sm_90+): 4x fewer RED ops than scalar atomicAdd
__device__ __forceinline__ void red_add_v4(float* p, float a, float b, float c, float d) {
    asm volatile("red.global.add.v4.f32 [%0], {%1,%2,%3,%4};"
                 :: "l"(p), "f"(a), "f"(b), "f"(c), "f"(d) : "memory");
}

// ---------------- dtype probe + index conversion ----------------
// int64 data with values < 2^31: every odd 32-bit word is 0.
// int32 data: odd words are real values; edge indices are uniform in [0,50000)
// (P(all 1024 zero) ~ 0), sorted batch reaches graph>=1 within first ~400 nodes.
__global__ void k_detect(const void* ei, const void* batch) {
    if (threadIdx.x == 0 && blockIdx.x == 0) {
        const int* w = (const int*)ei;
        int ok = 1;
        for (int k = 0; k < 1024; k++)
            if (w[2 * k + 1] != 0) { ok = 0; break; }
        g_is64_edge = ok;
        const int* b = (const int*)batch;
        int ok2 = 1;
        for (int k = 0; k < 1024; k++)
            if (b[2 * k + 1] != 0) { ok2 = 0; break; }
        g_is64_batch = ok2;
    }
}

__global__ void k_cvt_edge(const void* ei) {
    int e = blockIdx.x * blockDim.x + threadIdx.x;
    if (e >= NE) return;
    if (g_is64_edge) {
        const long long* p = (const long long*)ei;
        g_src[e] = (int)p[e];
        g_dst[e] = (int)p[NE + e];
    } else {
        const int* p = (const int*)ei;
        g_src[e] = p[e];
        g_dst[e] = p[NE + e];
    }
}

__global__ void k_cvt_batch(const void* batch) {
    int i = blockIdx.x * blockDim.x + threadIdx.x;
    if (i >= NN) return;
    if (g_is64_batch) {
        g_batch[i] = (int)((const long long*)batch)[i];
    } else {
        g_batch[i] = ((const int*)batch)[i];
    }
}

// ---------------- init: deg=1 (self loop), pool/cnt = 0 ----------------
__global__ void k_init() {
    int i = blockIdx.x * blockDim.x + threadIdx.x;
    if (i < NN) g_deg[i] = 1.0f;
    if (i < NG * EMB) g_pool[i] = 0.0f;
    if (i < NG) g_cnt[i] = 0.0f;
}

__global__ void k_deg(const float* __restrict__ ew) {
    int e = blockIdx.x * blockDim.x + threadIdx.x;
    if (e < NE) atomicAdd(&g_deg[g_dst[e]], ew[e]);
}

__global__ void k_dis() {
    int i = blockIdx.x * blockDim.x + threadIdx.x;
    if (i < NN) {
        float d = g_deg[i];
        g_dis[i] = d > 0.0f ? rsqrtf(d) : 0.0f;
    }
}

// ---------------- GEMM: C[node,OUT] = f(A[node,IN]) @ W[IN,OUT] ----------------
// warp-per-node; W staged in smem; x row staged via smem broadcast.
template <int IN, int OUT, bool BIASRELU>
__device__ __forceinline__ void gemm_body(const float* __restrict__ A,
                                          const float* __restrict__ W,
                                          const float* __restrict__ bias,
                                          float* __restrict__ C) {
    __shared__ float Ws[IN * OUT];
    __shared__ float bs[IN];
    __shared__ float xs[8][32];
    for (int i = threadIdx.x; i < IN * OUT; i += blockDim.x) Ws[i] = W[i];
    if (BIASRELU)
        for (int i = threadIdx.x; i < IN; i += blockDim.x) bs[i] = bias[i];
    __syncthreads();

    const int warp = threadIdx.x >> 5;
    const int lane = threadIdx.x & 31;
    constexpr int NC = OUT / 32;

    for (int node = blockIdx.x * 8 + warp; node < NN; node += gridDim.x * 8) {
        float acc[NC];
#pragma unroll
        for (int c = 0; c < NC; c++) acc[c] = 0.0f;
        const float* row = A + (size_t)node * IN;

        for (int kb = 0; kb < IN; kb += 32) {
            float xv = row[kb + lane];
            if (BIASRELU) xv = fmaxf(xv + bs[kb + lane], 0.0f);
            xs[warp][lane] = xv;
            __syncwarp();
#pragma unroll
            for (int kk = 0; kk < 32; kk++) {
                float xk = xs[warp][kk];
                const float* wr = Ws + (kb + kk) * OUT + lane;
#pragma unroll
                for (int c = 0; c < NC; c++) acc[c] = fmaf(xk, wr[32 * c], acc[c]);
            }
            __syncwarp();
        }
#pragma unroll
        for (int c = 0; c < NC; c++)
            C[(size_t)node * OUT + lane + 32 * c] = acc[c];
    }
}

__global__ void k_gemm1(const float* __restrict__ x, const float* __restrict__ W1) {
    gemm_body<IND, HID, false>(x, W1, nullptr, g_h1);
}
__global__ void k_gemm2(const float* __restrict__ W2, const float* __restrict__ b1) {
    gemm_body<HID, EMB, true>(g_a1, W2, b1, g_h2);
}

// ---------------- self-loop init: O[i,:] = dis[i]^2 * H[i,:] ----------------
template <int DIM>
__device__ __forceinline__ void self_body(const float* __restrict__ H, float* __restrict__ O) {
    int gid = blockIdx.x * blockDim.x + threadIdx.x;
    constexpr int G = DIM / 4;
    if (gid >= NN * G) return;
    int i = gid / G, l = gid % G;
    float s = g_dis[i];
    s *= s;
    float4 h = *(const float4*)(H + (size_t)i * DIM + 4 * l);
    float4 o = {h.x * s, h.y * s, h.z * s, h.w * s};
    *(float4*)(O + (size_t)i * DIM + 4 * l) = o;
}

__global__ void k_self1() { self_body<HID>(g_h1, g_a1); }
__global__ void k_self2() { self_body<EMB>(g_h2, g_a2); }

// ---------------- edge scatter: O[dst,:] += dis[src]*w*dis[dst] * H[src,:] ----------------
template <int DIM>
__device__ __forceinline__ void edge_body(const float* __restrict__ ew,
                                          const float* __restrict__ H,
                                          float* __restrict__ O) {
    constexpr int G = DIM / 4;  // threads per edge (one float4 each)
    int gid = blockIdx.x * blockDim.x + threadIdx.x;
    if (gid >= NE * G) return;
    int e = gid / G, l = gid % G;
    int s = g_src[e];
    int d = g_dst[e];
    float coef = g_dis[s] * ew[e] * g_dis[d];
    float4 h = *(const float4*)(H + (size_t)s * DIM + 4 * l);
    red_add_v4(O + (size_t)d * DIM + 4 * l,
               h.x * coef, h.y * coef, h.z * coef, h.w * coef);
}

__global__ void k_edge1(const float* __restrict__ ew) { edge_body<HID>(ew, g_h1, g_a1); }
__global__ void k_edge2(const float* __restrict__ ew) { edge_body<EMB>(ew, g_h2, g_a2); }

// ---------------- pooling: pool[g,:] += relu(a2[i,:]+b2), cnt[g]++ ----------------
__global__ void k_pool(const float* __restrict__ b2) {
    int gid = blockIdx.x * blockDim.x + threadIdx.x;
    if (gid >= NN * 32) return;
    int i = gid >> 5, l = gid & 31;
    int g = g_batch[i];
    float4 v = *(const float4*)(g_a2 + (size_t)i * EMB + 4 * l);
    float4 b = *(const float4*)(b2 + 4 * l);
    v.x = fmaxf(v.x + b.x, 0.0f);
    v.y = fmaxf(v.y + b.y, 0.0f);
    v.z = fmaxf(v.z + b.z, 0.0f);
    v.w = fmaxf(v.w + b.w, 0.0f);
    red_add_v4(g_pool + g * EMB + 4 * l, v.x, v.y, v.z, v.w);
}

__global__ void k_cnt() {
    int i = blockIdx.x * blockDim.x + threadIdx.x;
    if (i < NN) atomicAdd(&g_cnt[g_batch[i]], 1.0f);
}

__global__ void k_div(float* __restrict__ out) {
    int gid = blockIdx.x * blockDim.x + threadIdx.x;
    if (gid < NG * EMB) out[gid] = g_pool[gid] / fmaxf(g_cnt[gid >> 7], 1.0f);
}

// ---------------- launch ----------------
extern "C" void kernel_launch(void* const* d_in, const int* in_sizes, int n_in,
                              void* d_out, int out_size) {
    const float* x     = (const float*)d_in[0];
    const void*  ei    = d_in[1];  // [2, NE] int32 or int64 — probed on device
    const float* ew    = (const float*)d_in[2];
    const void*  batch = d_in[3];
    const float* W1    = (const float*)d_in[4];
    const float* b1    = (const float*)d_in[5];
    const float* W2    = (const float*)d_in[6];
    const float* b2    = (const float*)d_in[7];
    float*       out   = (float*)d_out;

    const int T = 256;
    k_detect<<<1, 32>>>(ei, batch);
    k_cvt_edge<<<(NE + T - 1) / T, T>>>(ei);
    k_cvt_batch<<<(NN + T - 1) / T, T>>>(batch);

    k_init<<<(NN + T - 1) / T, T>>>();
    k_deg<<<(NE + T - 1) / T, T>>>(ew);
    k_dis<<<(NN + T - 1) / T, T>>>();

    // layer 1
    k_gemm1<<<(NN + 7) / 8, T>>>(x, W1);
    k_self1<<<(NN * (HID / 4) + T - 1) / T, T>>>();
    k_edge1<<<(NE * (HID / 4) + T - 1) / T, T>>>(ew);

    // layer 2 (bias+relu fused into GEMM2 input load)
    k_gemm2<<<(NN + 7) / 8, T>>>(W2, b1);
    k_self2<<<(NN * (EMB / 4) + T - 1) / T, T>>>();
    k_edge2<<<(NE * (EMB / 4) + T - 1) / T, T>>>(ew);

    // pool (bias+relu fused) + mean
    k_pool<<<(NN * 32 + T - 1) / T, T>>>(b2);
    k_cnt<<<(NN + T - 1) / T, T>>>();
    k_div<<<(NG * EMB + T - 1) / T, T>>>(out);
}

// round 4
// speedup vs baseline: 1.0078x; 1.0078x over previous
#include <cuda_runtime.h>

#define NN 50000
#define NE 800000
#define NG 256
#define IND 128
#define HID 64
#define EMB 128

// ---------------- scratch (device globals; no allocation) ----------------
__device__ int g_src[NE];
__device__ int g_dst[NE];
__device__ int g_batch[NN];
__device__ int g_is64_edge;
__device__ int g_is64_batch;

__device__ float g_deg[NN];
__device__ float g_dis[NN];
__device__ alignas(16) float g_h1[(size_t)NN * HID];   // x @ W1
__device__ alignas(16) float g_a1[(size_t)NN * HID];   // aggregated layer 1 (pre-bias)
__device__ alignas(16) float g_h2[(size_t)NN * EMB];   // relu(a1+b1) @ W2
__device__ alignas(16) float g_a2[(size_t)NN * EMB];   // aggregated layer 2 (pre-bias)
__device__ alignas(16) float g_pool[NG * EMB];
__device__ float g_cnt[NG];

// vector f32 reduction (sm_90+): 4x fewer RED ops than scalar atomicAdd
__device__ __forceinline__ void red_add_v4(float* p, float a, float b, float c, float d) {
    asm volatile("red.global.add.v4.f32 [%0], {%1,%2,%3,%4};"
                 :: "l"(p), "f"(a), "f"(b), "f"(c), "f"(d) : "memory");
}

// ---------------- dtype probe + index conversion ----------------
// int64 data with values < 2^31: every odd 32-bit word is 0.
// int32 data: odd words are real values; edge indices are uniform in [0,50000)
// (P(all 1024 zero) ~ 0), sorted batch reaches graph>=1 within first ~400 nodes.
__global__ void k_detect(const void* ei, const void* batch) {
    if (threadIdx.x == 0 && blockIdx.x == 0) {
        const int* w = (const int*)ei;
        int ok = 1;
        for (int k = 0; k < 1024; k++)
            if (w[2 * k + 1] != 0) { ok = 0; break; }
        g_is64_edge = ok;
        const int* b = (const int*)batch;
        int ok2 = 1;
        for (int k = 0; k < 1024; k++)
            if (b[2 * k + 1] != 0) { ok2 = 0; break; }
        g_is64_batch = ok2;
    }
}

__global__ void k_cvt_edge(const void* ei) {
    int e = blockIdx.x * blockDim.x + threadIdx.x;
    if (e >= NE) return;
    if (g_is64_edge) {
        const long long* p = (const long long*)ei;
        g_src[e] = (int)p[e];
        g_dst[e] = (int)p[NE + e];
    } else {
        const int* p = (const int*)ei;
        g_src[e] = p[e];
        g_dst[e] = p[NE + e];
    }
}

__global__ void k_cvt_batch(const void* batch) {
    int i = blockIdx.x * blockDim.x + threadIdx.x;
    if (i >= NN) return;
    if (g_is64_batch) {
        g_batch[i] = (int)((const long long*)batch)[i];
    } else {
        g_batch[i] = ((const int*)batch)[i];
    }
}

// ---------------- init: deg=1 (self loop), pool/cnt = 0 ----------------
__global__ void k_init() {
    int i = blockIdx.x * blockDim.x + threadIdx.x;
    if (i < NN) g_deg[i] = 1.0f;
    if (i < NG * EMB) g_pool[i] = 0.0f;
    if (i < NG) g_cnt[i] = 0.0f;
}

__global__ void k_deg(const float* __restrict__ ew) {
    int e = blockIdx.x * blockDim.x + threadIdx.x;
    if (e < NE) atomicAdd(&g_deg[g_dst[e]], ew[e]);
}

__global__ void k_dis() {
    int i = blockIdx.x * blockDim.x + threadIdx.x;
    if (i < NN) {
        float d = g_deg[i];
        g_dis[i] = d > 0.0f ? rsqrtf(d) : 0.0f;
    }
}

// ---------------- GEMM: C[node,OUT] = f(A[node,IN]) @ W[IN,OUT] ----------------
// warp-per-node; W staged in smem; x row staged via smem broadcast.
template <int IN, int OUT, bool BIASRELU>
__device__ __forceinline__ void gemm_body(const float* __restrict__ A,
                                          const float* __restrict__ W,
                                          const float* __restrict__ bias,
                                          float* __restrict__ C) {
    __shared__ float Ws[IN * OUT];
    __shared__ float bs[IN];
    __shared__ float xs[8][32];
    for (int i = threadIdx.x; i < IN * OUT; i += blockDim.x) Ws[i] = W[i];
    if (BIASRELU)
        for (int i = threadIdx.x; i < IN; i += blockDim.x) bs[i] = bias[i];
    __syncthreads();

    const int warp = threadIdx.x >> 5;
    const int lane = threadIdx.x & 31;
    constexpr int NC = OUT / 32;

    for (int node = blockIdx.x * 8 + warp; node < NN; node += gridDim.x * 8) {
        float acc[NC];
#pragma unroll
        for (int c = 0; c < NC; c++) acc[c] = 0.0f;
        const float* row = A + (size_t)node * IN;

        for (int kb = 0; kb < IN; kb += 32) {
            float xv = row[kb + lane];
            if (BIASRELU) xv = fmaxf(xv + bs[kb + lane], 0.0f);
            xs[warp][lane] = xv;
            __syncwarp();
#pragma unroll
            for (int kk = 0; kk < 32; kk++) {
                float xk = xs[warp][kk];
                const float* wr = Ws + (kb + kk) * OUT + lane;
#pragma unroll
                for (int c = 0; c < NC; c++) acc[c] = fmaf(xk, wr[32 * c], acc[c]);
            }
            __syncwarp();
        }
#pragma unroll
        for (int c = 0; c < NC; c++)
            C[(size_t)node * OUT + lane + 32 * c] = acc[c];
    }
}

__global__ void k_gemm1(const float* __restrict__ x, const float* __restrict__ W1) {
    gemm_body<IND, HID, false>(x, W1, nullptr, g_h1);
}
__global__ void k_gemm2(const float* __restrict__ W2, const float* __restrict__ b1) {
    gemm_body<HID, EMB, true>(g_a1, W2, b1, g_h2);
}

// ---------------- self-loop init: O[i,:] = dis[i]^2 * H[i,:] ----------------
template <int DIM>
__device__ __forceinline__ void self_body(const float* __restrict__ H, float* __restrict__ O) {
    int gid = blockIdx.x * blockDim.x + threadIdx.x;
    constexpr int G = DIM / 4;
    if (gid >= NN * G) return;
    int i = gid / G, l = gid % G;
    float s = g_dis[i];
    s *= s;
    float4 h = *(const float4*)(H + (size_t)i * DIM + 4 * l);
    float4 o = {h.x * s, h.y * s, h.z * s, h.w * s};
    *(float4*)(O + (size_t)i * DIM + 4 * l) = o;
}

__global__ void k_self1() { self_body<HID>(g_h1, g_a1); }
__global__ void k_self2() { self_body<EMB>(g_h2, g_a2); }

// ---------------- edge scatter: O[dst,:] += dis[src]*w*dis[dst] * H[src,:] ----------------
template <int DIM>
__device__ __forceinline__ void edge_body(const float* __restrict__ ew,
                                          const float* __restrict__ H,
                                          float* __restrict__ O) {
    constexpr int G = DIM / 4;  // threads per edge (one float4 each)
    int gid = blockIdx.x * blockDim.x + threadIdx.x;
    if (gid >= NE * G) return;
    int e = gid / G, l = gid % G;
    int s = g_src[e];
    int d = g_dst[e];
    float coef = g_dis[s] * ew[e] * g_dis[d];
    float4 h = *(const float4*)(H + (size_t)s * DIM + 4 * l);
    red_add_v4(O + (size_t)d * DIM + 4 * l,
               h.x * coef, h.y * coef, h.z * coef, h.w * coef);
}

__global__ void k_edge1(const float* __restrict__ ew) { edge_body<HID>(ew, g_h1, g_a1); }
__global__ void k_edge2(const float* __restrict__ ew) { edge_body<EMB>(ew, g_h2, g_a2); }

// ---------------- pooling: pool[g,:] += relu(a2[i,:]+b2), cnt[g]++ ----------------
__global__ void k_pool(const float* __restrict__ b2) {
    int gid = blockIdx.x * blockDim.x + threadIdx.x;
    if (gid >= NN * 32) return;
    int i = gid >> 5, l = gid & 31;
    int g = g_batch[i];
    float4 v = *(const float4*)(g_a2 + (size_t)i * EMB + 4 * l);
    float4 b = *(const float4*)(b2 + 4 * l);
    v.x = fmaxf(v.x + b.x, 0.0f);
    v.y = fmaxf(v.y + b.y, 0.0f);
    v.z = fmaxf(v.z + b.z, 0.0f);
    v.w = fmaxf(v.w + b.w, 0.0f);
    red_add_v4(g_pool + g * EMB + 4 * l, v.x, v.y, v.z, v.w);
}

__global__ void k_cnt() {
    int i = blockIdx.x * blockDim.x + threadIdx.x;
    if (i < NN) atomicAdd(&g_cnt[g_batch[i]], 1.0f);
}

__global__ void k_div(float* __restrict__ out) {
    int gid = blockIdx.x * blockDim.x + threadIdx.x;
    if (gid < NG * EMB) out[gid] = g_pool[gid] / fmaxf(g_cnt[gid >> 7], 1.0f);
}

// ---------------- launch ----------------
extern "C" void kernel_launch(void* const* d_in, const int* in_sizes, int n_in,
                              void* d_out, int out_size) {
    const float* x     = (const float*)d_in[0];
    const void*  ei    = d_in[1];  // [2, NE] int32 or int64 — probed on device
    const float* ew    = (const float*)d_in[2];
    const void*  batch = d_in[3];
    const float* W1    = (const float*)d_in[4];
    const float* b1    = (const float*)d_in[5];
    const float* W2    = (const float*)d_in[6];
    const float* b2    = (const float*)d_in[7];
    float*       out   = (float*)d_out;

    const int T = 256;
    k_detect<<<1, 32>>>(ei, batch);
    k_cvt_edge<<<(NE + T - 1) / T, T>>>(ei);
    k_cvt_batch<<<(NN + T - 1) / T, T>>>(batch);

    k_init<<<(NN + T - 1) / T, T>>>();
    k_deg<<<(NE + T - 1) / T, T>>>(ew);
    k_dis<<<(NN + T - 1) / T, T>>>();

    // layer 1
    k_gemm1<<<(NN + 7) / 8, T>>>(x, W1);
    k_self1<<<(NN * (HID / 4) + T - 1) / T, T>>>();
    k_edge1<<<(NE * (HID / 4) + T - 1) / T, T>>>(ew);

    // layer 2 (bias+relu fused into GEMM2 input load)
    k_gemm2<<<(NN + 7) / 8, T>>>(W2, b1);
    k_self2<<<(NN * (EMB / 4) + T - 1) / T, T>>>();
    k_edge2<<<(NE * (EMB / 4) + T - 1) / T, T>>>(ew);

    // pool (bias+relu fused) + mean
    k_pool<<<(NN * 32 + T - 1) / T, T>>>(b2);
    k_cnt<<<(NN + T - 1) / T, T>>>();
    k_div<<<(NG * EMB + T - 1) / T, T>>>(out);
}

// round 5
// speedup vs baseline: 1.0100x; 1.0022x over previous
#include <cuda_runtime.h>

#define NN 50000
#define NE 800000
#define NG 256
#define IND 128
#define HID 64
#define EMB 128

// ---------------- scratch (device globals; no allocation) ----------------
__device__ int g_src[NE];
__device__ int g_dst[NE];
__device__ int g_batch[NN];
__device__ int g_is64_edge;
__device__ int g_is64_batch;

__device__ float g_deg[NN];
__device__ float g_dis[NN];
__device__ alignas(16) float g_h1[(size_t)NN * HID];   // x @ W1
__device__ alignas(16) float g_a1[(size_t)NN * HID];   // aggregated layer 1 (pre-bias)
__device__ alignas(16) float g_h2[(size_t)NN * EMB];   // relu(a1+b1) @ W2
__device__ alignas(16) float g_a2[(size_t)NN * EMB];   // aggregated layer 2 (pre-bias)
__device__ alignas(16) float g_pool[NG * EMB];
__device__ float g_cnt[NG];

// vector f32 reduction (sm_90+): 4x fewer RED ops than scalar atomicAdd
__device__ __forceinline__ void red_add_v4(float* p, float a, float b, float c, float d) {
    asm volatile("red.global.add.v4.f32 [%0], {%1,%2,%3,%4};"
                 :: "l"(p), "f"(a), "f"(b), "f"(c), "f"(d) : "memory");
}

// ---------------- dtype probe + index conversion ----------------
// int64 data with values < 2^31: every odd 32-bit word is 0.
// int32 data: odd words are real values; edge indices are uniform in [0,50000)
// (P(all 1024 zero) ~ 0), sorted batch reaches graph>=1 within first ~400 nodes.
__global__ void k_detect(const void* ei, const void* batch) {
    if (threadIdx.x == 0 && blockIdx.x == 0) {
        const int* w = (const int*)ei;
        int ok = 1;
        for (int k = 0; k < 1024; k++)
            if (w[2 * k + 1] != 0) { ok = 0; break; }
        g_is64_edge = ok;
        const int* b = (const int*)batch;
        int ok2 = 1;
        for (int k = 0; k < 1024; k++)
            if (b[2 * k + 1] != 0) { ok2 = 0; break; }
        g_is64_batch = ok2;
    }
}

__global__ void k_cvt_edge(const void* ei) {
    int e = blockIdx.x * blockDim.x + threadIdx.x;
    if (e >= NE) return;
    if (g_is64_edge) {
        const long long* p = (const long long*)ei;
        g_src[e] = (int)p[e];
        g_dst[e] = (int)p[NE + e];
    } else {
        const int* p = (const int*)ei;
        g_src[e] = p[e];
        g_dst[e] = p[NE + e];
    }
}

__global__ void k_cvt_batch(const void* batch) {
    int i = blockIdx.x * blockDim.x + threadIdx.x;
    if (i >= NN) return;
    if (g_is64_batch) {
        g_batch[i] = (int)((const long long*)batch)[i];
    } else {
        g_batch[i] = ((const int*)batch)[i];
    }
}

// ---------------- init: deg=1 (self loop), pool/cnt = 0 ----------------
__global__ void k_init() {
    int i = blockIdx.x * blockDim.x + threadIdx.x;
    if (i < NN) g_deg[i] = 1.0f;
    if (i < NG * EMB) g_pool[i] = 0.0f;
    if (i < NG) g_cnt[i] = 0.0f;
}

__global__ void k_deg(const float* __restrict__ ew) {
    int e = blockIdx.x * blockDim.x + threadIdx.x;
    if (e < NE) atomicAdd(&g_deg[g_dst[e]], ew[e]);
}

__global__ void k_dis() {
    int i = blockIdx.x * blockDim.x + threadIdx.x;
    if (i < NN) {
        float d = g_deg[i];
        g_dis[i] = d > 0.0f ? rsqrtf(d) : 0.0f;
    }
}

// ---------------- GEMM: C[node,OUT] = f(A[node,IN]) @ W[IN,OUT] ----------------
// warp-per-node; W staged in smem; x row staged via smem broadcast.
template <int IN, int OUT, bool BIASRELU>
__device__ __forceinline__ void gemm_body(const float* __restrict__ A,
                                          const float* __restrict__ W,
                                          const float* __restrict__ bias,
                                          float* __restrict__ C) {
    __shared__ float Ws[IN * OUT];
    __shared__ float bs[IN];
    __shared__ float xs[8][32];
    for (int i = threadIdx.x; i < IN * OUT; i += blockDim.x) Ws[i] = W[i];
    if (BIASRELU)
        for (int i = threadIdx.x; i < IN; i += blockDim.x) bs[i] = bias[i];
    __syncthreads();

    const int warp = threadIdx.x >> 5;
    const int lane = threadIdx.x & 31;
    constexpr int NC = OUT / 32;

    for (int node = blockIdx.x * 8 + warp; node < NN; node += gridDim.x * 8) {
        float acc[NC];
#pragma unroll
        for (int c = 0; c < NC; c++) acc[c] = 0.0f;
        const float* row = A + (size_t)node * IN;

        for (int kb = 0; kb < IN; kb += 32) {
            float xv = row[kb + lane];
            if (BIASRELU) xv = fmaxf(xv + bs[kb + lane], 0.0f);
            xs[warp][lane] = xv;
            __syncwarp();
#pragma unroll
            for (int kk = 0; kk < 32; kk++) {
                float xk = xs[warp][kk];
                const float* wr = Ws + (kb + kk) * OUT + lane;
#pragma unroll
                for (int c = 0; c < NC; c++) acc[c] = fmaf(xk, wr[32 * c], acc[c]);
            }
            __syncwarp();
        }
#pragma unroll
        for (int c = 0; c < NC; c++)
            C[(size_t)node * OUT + lane + 32 * c] = acc[c];
    }
}

__global__ void k_gemm1(const float* __restrict__ x, const float* __restrict__ W1) {
    gemm_body<IND, HID, false>(x, W1, nullptr, g_h1);
}
__global__ void k_gemm2(const float* __restrict__ W2, const float* __restrict__ b1) {
    gemm_body<HID, EMB, true>(g_a1, W2, b1, g_h2);
}

// ---------------- self-loop init: O[i,:] = dis[i]^2 * H[i,:] ----------------
template <int DIM>
__device__ __forceinline__ void self_body(const float* __restrict__ H, float* __restrict__ O) {
    int gid = blockIdx.x * blockDim.x + threadIdx.x;
    constexpr int G = DIM / 4;
    if (gid >= NN * G) return;
    int i = gid / G, l = gid % G;
    float s = g_dis[i];
    s *= s;
    float4 h = *(const float4*)(H + (size_t)i * DIM + 4 * l);
    float4 o = {h.x * s, h.y * s, h.z * s, h.w * s};
    *(float4*)(O + (size_t)i * DIM + 4 * l) = o;
}

__global__ void k_self1() { self_body<HID>(g_h1, g_a1); }
__global__ void k_self2() { self_body<EMB>(g_h2, g_a2); }

// ---------------- edge scatter: O[dst,:] += dis[src]*w*dis[dst] * H[src,:] ----------------
template <int DIM>
__device__ __forceinline__ void edge_body(const float* __restrict__ ew,
                                          const float* __restrict__ H,
                                          float* __restrict__ O) {
    constexpr int G = DIM / 4;  // threads per edge (one float4 each)
    int gid = blockIdx.x * blockDim.x + threadIdx.x;
    if (gid >= NE * G) return;
    int e = gid / G, l = gid % G;
    int s = g_src[e];
    int d = g_dst[e];
    float coef = g_dis[s] * ew[e] * g_dis[d];
    float4 h = *(const float4*)(H + (size_t)s * DIM + 4 * l);
    red_add_v4(O + (size_t)d * DIM + 4 * l,
               h.x * coef, h.y * coef, h.z * coef, h.w * coef);
}

__global__ void k_edge1(const float* __restrict__ ew) { edge_body<HID>(ew, g_h1, g_a1); }
__global__ void k_edge2(const float* __restrict__ ew) { edge_body<EMB>(ew, g_h2, g_a2); }

// ---------------- pooling: pool[g,:] += relu(a2[i,:]+b2), cnt[g]++ ----------------
__global__ void k_pool(const float* __restrict__ b2) {
    int gid = blockIdx.x * blockDim.x + threadIdx.x;
    if (gid >= NN * 32) return;
    int i = gid >> 5, l = gid & 31;
    int g = g_batch[i];
    float4 v = *(const float4*)(g_a2 + (size_t)i * EMB + 4 * l);
    float4 b = *(const float4*)(b2 + 4 * l);
    v.x = fmaxf(v.x + b.x, 0.0f);
    v.y = fmaxf(v.y + b.y, 0.0f);
    v.z = fmaxf(v.z + b.z, 0.0f);
    v.w = fmaxf(v.w + b.w, 0.0f);
    red_add_v4(g_pool + g * EMB + 4 * l, v.x, v.y, v.z, v.w);
}

__global__ void k_cnt() {
    int i = blockIdx.x * blockDim.x + threadIdx.x;
    if (i < NN) atomicAdd(&g_cnt[g_batch[i]], 1.0f);
}

__global__ void k_div(float* __restrict__ out) {
    int gid = blockIdx.x * blockDim.x + threadIdx.x;
    if (gid < NG * EMB) out[gid] = g_pool[gid] / fmaxf(g_cnt[gid >> 7], 1.0f);
}

// ---------------- launch ----------------
extern "C" void kernel_launch(void* const* d_in, const int* in_sizes, int n_in,
                              void* d_out, int out_size) {
    const float* x     = (const float*)d_in[0];
    const void*  ei    = d_in[1];  // [2, NE] int32 or int64 — probed on device
    const float* ew    = (const float*)d_in[2];
    const void*  batch = d_in[3];
    const float* W1    = (const float*)d_in[4];
    const float* b1    = (const float*)d_in[5];
    const float* W2    = (const float*)d_in[6];
    const float* b2    = (const float*)d_in[7];
    float*       out   = (float*)d_out;

    const int T = 256;
    k_detect<<<1, 32>>>(ei, batch);
    k_cvt_edge<<<(NE + T - 1) / T, T>>>(ei);
    k_cvt_batch<<<(NN + T - 1) / T, T>>>(batch);

    k_init<<<(NN + T - 1) / T, T>>>();
    k_deg<<<(NE + T - 1) / T, T>>>(ew);
    k_dis<<<(NN + T - 1) / T, T>>>();

    // layer 1
    k_gemm1<<<(NN + 7) / 8, T>>>(x, W1);
    k_self1<<<(NN * (HID / 4) + T - 1) / T, T>>>();
    k_edge1<<<(NE * (HID / 4) + T - 1) / T, T>>>(ew);

    // layer 2 (bias+relu fused into GEMM2 input load)
    k_gemm2<<<(NN + 7) / 8, T>>>(W2, b1);
    k_self2<<<(NN * (EMB / 4) + T - 1) / T, T>>>();
    k_edge2<<<(NE * (EMB / 4) + T - 1) / T, T>>>(ew);

    // pool (bias+relu fused) + mean
    k_pool<<<(NN * 32 + T - 1) / T, T>>>(b2);
    k_cnt<<<(NN + T - 1) / T, T>>>();
    k_div<<<(NG * EMB + T - 1) / T, T>>>(out);
}